// round 15
// baseline (speedup 1.0000x reference)
#include <cuda_runtime.h>
#include <cuda_bf16.h>
#include <cstdint>

// ---------------------------------------------------------------------------
// WaveFDTD2D, temporal blocking K=4, 128 persistent CTAs x 1024 threads.
// ty 0..7: slot0 = row ty (0..7), slot1 = row ty+8 (8..11, ty<4 only).
// m/o/cf register-resident; ping-pong SMEM field images; neighbor-only
// monotonic-counter sync; hoisted invariant addresses/flags (R13).
// 32 warps/SM to hide LDS + barrier + L2 latency.
// ---------------------------------------------------------------------------

#define NX      512
#define NZ      512
#define NSTEPS  512
#define NREC    128
#define KST     4
#define NBLK    (NSTEPS / KST)     // 128
#define NCTA    128
#define NTHR    1024
#define RROWS   4
#define EXT     12
#define SROW    520
#define BUF     (EXT * SROW)
#define SMEM_FLOATS (2 * BUF)
#define SMEM_BYTES  (SMEM_FLOATS * 4)
#define PAD     32

__device__ __align__(16) float g_P[2][NX * NZ];
__device__ __align__(16) float g_Q[2][NX * NZ];
__device__ unsigned long long g_done[NCTA * PAD];   // monotonic, never reset

static __device__ __forceinline__ void signal_done(int bid) {
    asm volatile("red.add.release.gpu.u64 [%0], 1;"
                 :: "l"(&g_done[bid * PAD]) : "memory");
}

static __device__ __forceinline__ void wait_neighbors(int bid, unsigned long long tgt) {
    const unsigned long long* lo =
        (bid > 0) ? &g_done[(bid - 1) * PAD] : nullptr;
    const unsigned long long* hi =
        (bid < NCTA - 1) ? &g_done[(bid + 1) * PAD] : nullptr;
    bool need_lo = (lo != nullptr), need_hi = (hi != nullptr);
    while (need_lo || need_hi) {
        unsigned long long a = tgt, b = tgt;
        if (need_lo)
            asm volatile("ld.acquire.gpu.u64 %0, [%1];" : "=l"(a) : "l"(lo) : "memory");
        if (need_hi)
            asm volatile("ld.acquire.gpu.u64 %0, [%1];" : "=l"(b) : "l"(hi) : "memory");
        if (a >= tgt) need_lo = false;
        if (b >= tgt) need_hi = false;
    }
}

// One row (4 cells). All addresses/flags precomputed.
static __device__ __forceinline__ void row_update(
    const float* __restrict__ Scur, float* __restrict__ Snext,
    float4& m, float4& o, const float4 cf,
    const int sb,
    const bool do_store, float* __restrict__ gdst, const int go,
    const bool isrc, const float4 smask,
    const float* __restrict__ source, const int t)
{
    const float INV  = 0.01f;    // 1/(dx*dz)
    const float DT2f = 1.0e-6f;  // dt^2

    const float4 u  = *reinterpret_cast<const float4*>(Scur + sb - SROW);
    const float4 d  = *reinterpret_cast<const float4*>(Scur + sb + SROW);
    const float  lf = Scur[sb - 1];
    const float  rg = Scur[sb + 4];

    float4 nw; float lap;
    lap  = ((((u.x + d.x) + lf)  + m.y) - 4.0f * m.x) * INV;
    nw.x = (2.0f * m.x - o.x) + cf.x * lap;
    lap  = ((((u.y + d.y) + m.x) + m.z) - 4.0f * m.y) * INV;
    nw.y = (2.0f * m.y - o.y) + cf.y * lap;
    lap  = ((((u.z + d.z) + m.y) + m.w) - 4.0f * m.z) * INV;
    nw.z = (2.0f * m.z - o.z) + cf.z * lap;
    lap  = ((((u.w + d.w) + m.z) + rg)  - 4.0f * m.w) * INV;
    nw.w = (2.0f * m.w - o.w) + cf.w * lap;

    if (isrc) {
        const float sadd = __ldg(source + t) * DT2f;
        nw.x += smask.x * sadd;
        nw.y += smask.y * sadd;
        nw.z += smask.z * sadd;
        nw.w += smask.w * sadd;
    }
    *reinterpret_cast<float4*>(Snext + sb) = nw;
    if (do_store) {
        __stcg(reinterpret_cast<float4*>(gdst + go), nw);
    }
    o = m;
    m = nw;
}

__global__ void __launch_bounds__(NTHR, 1)
wave_fdtd_reg_kernel(const float* __restrict__ vel,
                     const float* __restrict__ source,
                     const int*   __restrict__ p_srcx,
                     const int*   __restrict__ p_srcz,
                     const int*   __restrict__ rec_x,
                     const int*   __restrict__ rec_z,
                     float*       __restrict__ out)
{
    extern __shared__ float sm[];
    __shared__ unsigned long long sm_base;
    float* S0 = sm;
    float* S1 = sm + BUF;

    const int tid = threadIdx.x;
    const int bid = blockIdx.x;
    const int g0  = bid * RROWS;
    const int tx  = tid & 127;
    const int ty  = tid >> 7;        // 0..7
    const int colbase = 4 + tx * 4;

    const int sx = p_srcx[0];
    const int sz = p_srcz[0];

    const int r0 = ty;               // 0..7
    const int r1 = ty + 8;           // 8..15 (slot exists only if <=11)
    const bool has1 = (ty < 4);      // slot1 rows 8..11
    const int ga = g0 - 4 + r0;
    const int gb = g0 - 4 + r1;
    const bool ing0 = (unsigned)ga < (unsigned)NX;
    const bool ing1 = has1 && ((unsigned)gb < (unsigned)NX);

    // ---- hoisted invariants ----
    const int sb0 = r0 * SROW + colbase;
    const int sb1 = r1 * SROW + colbase;
    const int go0 = ga * NZ + tx * 4;
    const int go1 = gb * NZ + tx * 4;
    const int clo = 4 - g0;
    const int chi = 515 - g0;

    // slot0 validity per substep (r0 <= 7 <= HI always; r0 vs LO/clo)
    const bool v0s1 = ing0 && (r0 >= ((clo > 1) ? clo : 1));
    const bool v0s2 = ing0 && (r0 >= ((clo > 2) ? clo : 2));
    const bool v0s3 = ing0 && (r0 >= ((clo > 3) ? clo : 3));
    const bool v0s4 = (r0 >= 4);                  // rows 4..7 always in-grid
    // slot1 validity (r1 >= 8 >= LO always; r1 vs HI/chi); s4 never uses slot1
    const bool v1s1 = ing1 && (r1 <= ((chi < 10) ? chi : 10));
    const bool v1s2 = ing1 && (r1 <= ((chi < 9) ? chi : 9));
    const bool v1s3 = ing1 && (r1 <= ((chi < 8) ? chi : 8));

    // own-row store: all own rows (4..7) live in slot0
    const bool st0 = (r0 >= 4);

    // halo refresh roles
    const bool h0    = (r0 <= 3) && ing0;         // rows 0..3
    const bool h1    = ing1;                      // rows 8..11
    const bool h0om  = (r0 == 3);
    const bool h0old = (r0 == 1) || (r0 == 2);
    const bool h1om  = (r1 == 8);
    const bool h1old = (r1 == 9) || (r1 == 10);

    // source injection
    const bool isrc0 = ing0 && (ga == sx) && ((sz >> 2) == tx);
    const bool isrc1 = ing1 && (gb == sx) && ((sz >> 2) == tx);
    const int  sl = sz & 3;
    const float4 smask = make_float4((sl == 0) ? 1.f : 0.f, (sl == 1) ? 1.f : 0.f,
                                     (sl == 2) ? 1.f : 0.f, (sl == 3) ? 1.f : 0.f);

    int my_rx = -1, my_rz = 0;
    if (tid < NREC) { my_rx = __ldg(rec_x + tid); my_rz = __ldg(rec_z + tid); }
    const bool my_rec = (my_rx >= 0) && ((my_rx >> 2) == bid);
    const int  rec_off = my_rec ? ((4 + (my_rx & 3)) * SROW + 4 + my_rz) : 0;
    float* const outp = out + (size_t)tid * NSTEPS;

    // ---- zero SMEM; read own counter base ----
    for (int i = tid; i < SMEM_FLOATS; i += NTHR) sm[i] = 0.0f;
    if (tid == 0) sm_base = g_done[bid * PAD];
    __syncthreads();
    const unsigned long long base = sm_base;

    // ---- register state ----
    const float DT2f = 1.0e-6f;
    float4 m0 = make_float4(0.f,0.f,0.f,0.f), o0 = m0, cf0 = m0;
    float4 m1 = m0, o1 = m0, cf1 = m0;
    if (ing0) {
        const float4 v = __ldg(reinterpret_cast<const float4*>(vel + go0));
        cf0 = make_float4(v.x*v.x*DT2f, v.y*v.y*DT2f, v.z*v.z*DT2f, v.w*v.w*DT2f);
    }
    if (ing1) {
        const float4 v = __ldg(reinterpret_cast<const float4*>(vel + go1));
        cf1 = make_float4(v.x*v.x*DT2f, v.y*v.y*DT2f, v.z*v.z*DT2f, v.w*v.w*DT2f);
    }

    // ---- zero OWN rows of global pair 0 ----
    if (tid < RROWS * 128) {
        const float4 z = make_float4(0.f, 0.f, 0.f, 0.f);
        const int r = tid >> 7, c = tid & 127;
        const int off = (g0 + r) * NZ + c * 4;
        __stcg(reinterpret_cast<float4*>(g_P[0] + off), z);
        __stcg(reinterpret_cast<float4*>(g_Q[0] + off), z);
    }
    __syncthreads();
    if (tid == 0) signal_done(bid);

    for (int b = 0; b < NBLK; ++b) {
        if (tid == 0)
            wait_neighbors(bid, base + 1 + (unsigned long long)b);
        __syncthreads();

        const int pb = b & 1;
        const float* gp = g_P[pb];
        const float* gq = g_Q[pb];

        // ---- halo refresh ----
        if (h0) {
            const float4 v = __ldcg(reinterpret_cast<const float4*>(gp + go0));
            if (h0om)       o0 = m0;
            else if (h0old) o0 = __ldcg(reinterpret_cast<const float4*>(gq + go0));
            m0 = v;
            *reinterpret_cast<float4*>(S0 + sb0) = v;
        }
        if (h1) {
            const float4 v = __ldcg(reinterpret_cast<const float4*>(gp + go1));
            if (h1om)       o1 = m1;
            else if (h1old) o1 = __ldcg(reinterpret_cast<const float4*>(gq + go1));
            m1 = v;
            *reinterpret_cast<float4*>(S0 + sb1) = v;
        }
        __syncthreads();

        const int t0 = b * KST;
        float* gpo = g_P[pb ^ 1];
        float* gqo = g_Q[pb ^ 1];

        // s1: rows [1,10], S0 -> S1
        if (v0s1) row_update(S0, S1, m0, o0, cf0, sb0, false, nullptr, 0,
                             isrc0, smask, source, t0);
        if (v1s1) row_update(S0, S1, m1, o1, cf1, sb1, false, nullptr, 0,
                             isrc1, smask, source, t0);
        __syncthreads();
        if (my_rec) outp[t0] = S1[rec_off];

        // s2: rows [2,9], S1 -> S0
        if (v0s2) row_update(S1, S0, m0, o0, cf0, sb0, false, nullptr, 0,
                             isrc0, smask, source, t0 + 1);
        if (v1s2) row_update(S1, S0, m1, o1, cf1, sb1, false, nullptr, 0,
                             isrc1, smask, source, t0 + 1);
        __syncthreads();
        if (my_rec) outp[t0 + 1] = S0[rec_off];

        // s3: rows [3,8], S0 -> S1; own rows -> Q[pb^1]
        if (v0s3) row_update(S0, S1, m0, o0, cf0, sb0, st0, gqo, go0,
                             isrc0, smask, source, t0 + 2);
        if (v1s3) row_update(S0, S1, m1, o1, cf1, sb1, false, gqo, go1,
                             isrc1, smask, source, t0 + 2);
        __syncthreads();
        if (my_rec) outp[t0 + 2] = S1[rec_off];

        // s4: rows [4,7], S1 -> S0; own rows -> P[pb^1] (slot0 only)
        if (v0s4) row_update(S1, S0, m0, o0, cf0, sb0, st0, gpo, go0,
                             isrc0, smask, source, t0 + 3);
        __syncthreads();
        if (my_rec) outp[t0 + 3] = S0[rec_off];

        if (tid == 0) signal_done(bid);
    }
}

extern "C" void kernel_launch(void* const* d_in, const int* in_sizes, int n_in,
                              void* d_out, int out_size)
{
    const float* vel    = (const float*)d_in[0];
    const float* source = (const float*)d_in[1];
    const int*   srcx   = (const int*)d_in[2];
    const int*   srcz   = (const int*)d_in[3];
    const int*   rec_x  = (const int*)d_in[4];
    const int*   rec_z  = (const int*)d_in[5];
    float* out = (float*)d_out;

    cudaFuncSetAttribute(wave_fdtd_reg_kernel,
                         cudaFuncAttributeMaxDynamicSharedMemorySize, SMEM_BYTES);
    wave_fdtd_reg_kernel<<<NCTA, NTHR, SMEM_BYTES>>>(
        vel, source, srcx, srcz, rec_x, rec_z, out);
}

// round 16
// speedup vs baseline: 1.0250x; 1.0250x over previous
#include <cuda_runtime.h>
#include <cuda_bf16.h>
#include <cstdint>

// ---------------------------------------------------------------------------
// WaveFDTD2D, temporal blocking K=4, 128 persistent CTAs x 768 threads.
// Thread (tx,ty), ty in 0..5, owns rows {ty, ty+6}. m/o/cf register-resident.
// R15: per-warp release signaling (counter unit = 24 per block) + all-thread
// neighbor spin + deferred s4 receiver gather -> 4 CTA barriers per block
// instead of 6, and the inter-CTA wait + halo L2 loads overlap s4 drain.
// ---------------------------------------------------------------------------

#define NX      512
#define NZ      512
#define NSTEPS  512
#define NREC    128
#define KST     4
#define NBLK    (NSTEPS / KST)     // 128
#define NCTA    128
#define NTHR    768
#define NWARP   (NTHR / 32)        // 24 signals per block
#define RROWS   4
#define EXT     12
#define SROW    520
#define BUF     (EXT * SROW)
#define SMEM_FLOATS (2 * BUF)
#define SMEM_BYTES  (SMEM_FLOATS * 4)
#define PAD     32

__device__ __align__(16) float g_P[2][NX * NZ];
__device__ __align__(16) float g_Q[2][NX * NZ];
__device__ unsigned long long g_done[NCTA * PAD];   // monotonic, never reset

// Per-warp signal: __syncwarp() orders all 32 lanes' prior stores; lane-0's
// release-reduction is cumulative over them (PTX scoped release).
static __device__ __forceinline__ void warp_signal(int bid, int tid) {
    __syncwarp();
    if ((tid & 31) == 0) {
        asm volatile("red.add.release.gpu.u64 [%0], 1;"
                     :: "l"(&g_done[bid * PAD]) : "memory");
    }
}

// Every thread spins until both neighbor counters reach tgt (warp-uniform).
static __device__ __forceinline__ void wait_neighbors_all(int bid, unsigned long long tgt) {
    const unsigned long long* lo =
        (bid > 0) ? &g_done[(bid - 1) * PAD] : nullptr;
    const unsigned long long* hi =
        (bid < NCTA - 1) ? &g_done[(bid + 1) * PAD] : nullptr;
    bool need_lo = (lo != nullptr), need_hi = (hi != nullptr);
    while (need_lo || need_hi) {
        unsigned long long a = tgt, b = tgt;
        if (need_lo)
            asm volatile("ld.acquire.gpu.u64 %0, [%1];" : "=l"(a) : "l"(lo) : "memory");
        if (need_hi)
            asm volatile("ld.acquire.gpu.u64 %0, [%1];" : "=l"(b) : "l"(hi) : "memory");
        if (a >= tgt) need_lo = false;
        if (b >= tgt) need_hi = false;
    }
}

// One row (4 cells). All addresses/flags precomputed.
static __device__ __forceinline__ void row_update(
    const float* __restrict__ Scur, float* __restrict__ Snext,
    float4& m, float4& o, const float4 cf,
    const int sb,
    const bool do_store, float* __restrict__ gdst, const int go,
    const bool isrc, const float4 smask,
    const float* __restrict__ source, const int t)
{
    const float INV  = 0.01f;    // 1/(dx*dz)
    const float DT2f = 1.0e-6f;  // dt^2

    const float4 u  = *reinterpret_cast<const float4*>(Scur + sb - SROW);
    const float4 d  = *reinterpret_cast<const float4*>(Scur + sb + SROW);
    const float  lf = Scur[sb - 1];
    const float  rg = Scur[sb + 4];

    float4 nw; float lap;
    lap  = ((((u.x + d.x) + lf)  + m.y) - 4.0f * m.x) * INV;
    nw.x = (2.0f * m.x - o.x) + cf.x * lap;
    lap  = ((((u.y + d.y) + m.x) + m.z) - 4.0f * m.y) * INV;
    nw.y = (2.0f * m.y - o.y) + cf.y * lap;
    lap  = ((((u.z + d.z) + m.y) + m.w) - 4.0f * m.z) * INV;
    nw.z = (2.0f * m.z - o.z) + cf.z * lap;
    lap  = ((((u.w + d.w) + m.z) + rg)  - 4.0f * m.w) * INV;
    nw.w = (2.0f * m.w - o.w) + cf.w * lap;

    if (isrc) {
        const float sadd = __ldg(source + t) * DT2f;
        nw.x += smask.x * sadd;
        nw.y += smask.y * sadd;
        nw.z += smask.z * sadd;
        nw.w += smask.w * sadd;
    }
    *reinterpret_cast<float4*>(Snext + sb) = nw;
    if (do_store) {
        __stcg(reinterpret_cast<float4*>(gdst + go), nw);
    }
    o = m;
    m = nw;
}

__global__ void __launch_bounds__(NTHR, 1)
wave_fdtd_reg_kernel(const float* __restrict__ vel,
                     const float* __restrict__ source,
                     const int*   __restrict__ p_srcx,
                     const int*   __restrict__ p_srcz,
                     const int*   __restrict__ rec_x,
                     const int*   __restrict__ rec_z,
                     float*       __restrict__ out)
{
    extern __shared__ float sm[];
    __shared__ unsigned long long sm_base;
    float* S0 = sm;
    float* S1 = sm + BUF;

    const int tid = threadIdx.x;
    const int bid = blockIdx.x;
    const int g0  = bid * RROWS;
    const int tx  = tid & 127;
    const int ty  = tid >> 7;        // 0..5
    const int colbase = 4 + tx * 4;

    const int sx = p_srcx[0];
    const int sz = p_srcz[0];

    const int r0 = ty;               // 0..5
    const int r1 = ty + 6;           // 6..11
    const int ga = g0 - 4 + r0;
    const int gb = g0 - 4 + r1;
    const bool ing0 = (unsigned)ga < (unsigned)NX;
    const bool ing1 = (unsigned)gb < (unsigned)NX;

    // ---- hoisted invariants ----
    const int sb0 = r0 * SROW + colbase;
    const int sb1 = r1 * SROW + colbase;
    const int go0 = ga * NZ + tx * 4;
    const int go1 = gb * NZ + tx * 4;
    const int clo = 4 - g0;
    const int chi = 515 - g0;

    const bool v0s1 = ing0 && (r0 >= ((clo > 1) ? clo : 1));
    const bool v0s2 = ing0 && (r0 >= ((clo > 2) ? clo : 2));
    const bool v0s3 = ing0 && (r0 >= ((clo > 3) ? clo : 3));
    const bool v0s4 = ing0 && (r0 >= 4);
    const bool v1s1 = ing1 && (r1 <= ((chi < 10) ? chi : 10));
    const bool v1s2 = ing1 && (r1 <= ((chi < 9) ? chi : 9));
    const bool v1s3 = ing1 && (r1 <= ((chi < 8) ? chi : 8));
    const bool v1s4 = ing1 && (r1 <= 7);

    const bool st0 = (r0 >= 4);              // rows 4,5
    const bool st1 = (r1 <= 7);              // rows 6,7

    const bool h0    = (r0 <= 3) && ing0;    // rows 0..3
    const bool h1    = (r1 >= 8) && ing1;    // rows 8..11
    const bool h0om  = (r0 == 3);
    const bool h0old = (r0 == 1) || (r0 == 2);
    const bool h1om  = (r1 == 8);
    const bool h1old = (r1 == 9) || (r1 == 10);

    const bool isrc0 = ing0 && (ga == sx) && ((sz >> 2) == tx);
    const bool isrc1 = ing1 && (gb == sx) && ((sz >> 2) == tx);
    const int  sl = sz & 3;
    const float4 smask = make_float4((sl == 0) ? 1.f : 0.f, (sl == 1) ? 1.f : 0.f,
                                     (sl == 2) ? 1.f : 0.f, (sl == 3) ? 1.f : 0.f);

    int my_rx = -1, my_rz = 0;
    if (tid < NREC) { my_rx = __ldg(rec_x + tid); my_rz = __ldg(rec_z + tid); }
    const bool my_rec = (my_rx >= 0) && ((my_rx >> 2) == bid);
    const int  rec_off = my_rec ? ((4 + (my_rx & 3)) * SROW + 4 + my_rz) : 0;
    float* const outp = out + (size_t)tid * NSTEPS;

    // ---- read own counter base FIRST (before any signal this launch) ----
    if (tid == 0) sm_base = g_done[bid * PAD];
    // ---- zero SMEM ----
    for (int i = tid; i < SMEM_FLOATS; i += NTHR) sm[i] = 0.0f;
    __syncthreads();                       // base read + SMEM zero complete
    const unsigned long long base = sm_base;

    // ---- register state ----
    const float DT2f = 1.0e-6f;
    float4 m0 = make_float4(0.f,0.f,0.f,0.f), o0 = m0, cf0 = m0;
    float4 m1 = m0, o1 = m0, cf1 = m0;
    if (ing0) {
        const float4 v = __ldg(reinterpret_cast<const float4*>(vel + go0));
        cf0 = make_float4(v.x*v.x*DT2f, v.y*v.y*DT2f, v.z*v.z*DT2f, v.w*v.w*DT2f);
    }
    if (ing1) {
        const float4 v = __ldg(reinterpret_cast<const float4*>(vel + go1));
        cf1 = make_float4(v.x*v.x*DT2f, v.y*v.y*DT2f, v.z*v.z*DT2f, v.w*v.w*DT2f);
    }

    // ---- zero OWN rows of global pair 0, then per-warp init signal ----
    if (tid < RROWS * 128) {
        const float4 z = make_float4(0.f, 0.f, 0.f, 0.f);
        const int r = tid >> 7, c = tid & 127;
        const int off = (g0 + r) * NZ + c * 4;
        __stcg(reinterpret_cast<float4*>(g_P[0] + off), z);
        __stcg(reinterpret_cast<float4*>(g_Q[0] + off), z);
    }
    warp_signal(bid, tid);                 // counters += 24 total (init)

    for (int b = 0; b < NBLK; ++b) {
        // ---- all threads spin; overlaps with own slow warps finishing s4 ----
        wait_neighbors_all(bid, base + (unsigned long long)(b + 1) * NWARP);

        const int pb = b & 1;
        const float* gp = g_P[pb];
        const float* gq = g_Q[pb];

        // ---- halo refresh (disjoint from s4's S0 rows 4..7) ----
        if (h0) {
            const float4 v = __ldcg(reinterpret_cast<const float4*>(gp + go0));
            if (h0om)       o0 = m0;
            else if (h0old) o0 = __ldcg(reinterpret_cast<const float4*>(gq + go0));
            m0 = v;
            *reinterpret_cast<float4*>(S0 + sb0) = v;
        }
        if (h1) {
            const float4 v = __ldcg(reinterpret_cast<const float4*>(gp + go1));
            if (h1om)       o1 = m1;
            else if (h1old) o1 = __ldcg(reinterpret_cast<const float4*>(gq + go1));
            m1 = v;
            *reinterpret_cast<float4*>(S0 + sb1) = v;
        }
        __syncthreads();   // halo staged + ALL warps' prev s4 writes visible

        // ---- deferred gather of previous block's s4 (S0 rows 4..7 intact) ----
        if (b > 0 && my_rec) outp[b * KST - 1] = S0[rec_off];

        const int t0 = b * KST;
        float* gpo = g_P[pb ^ 1];
        float* gqo = g_Q[pb ^ 1];

        // s1: rows [1,10], S0 -> S1
        if (v0s1) row_update(S0, S1, m0, o0, cf0, sb0, false, nullptr, 0,
                             isrc0, smask, source, t0);
        if (v1s1) row_update(S0, S1, m1, o1, cf1, sb1, false, nullptr, 0,
                             isrc1, smask, source, t0);
        __syncthreads();
        if (my_rec) outp[t0] = S1[rec_off];

        // s2: rows [2,9], S1 -> S0
        if (v0s2) row_update(S1, S0, m0, o0, cf0, sb0, false, nullptr, 0,
                             isrc0, smask, source, t0 + 1);
        if (v1s2) row_update(S1, S0, m1, o1, cf1, sb1, false, nullptr, 0,
                             isrc1, smask, source, t0 + 1);
        __syncthreads();
        if (my_rec) outp[t0 + 1] = S0[rec_off];

        // s3: rows [3,8], S0 -> S1; own rows -> Q[pb^1]
        if (v0s3) row_update(S0, S1, m0, o0, cf0, sb0, st0, gqo, go0,
                             isrc0, smask, source, t0 + 2);
        if (v1s3) row_update(S0, S1, m1, o1, cf1, sb1, st1, gqo, go1,
                             isrc1, smask, source, t0 + 2);
        __syncthreads();
        if (my_rec) outp[t0 + 2] = S1[rec_off];

        // s4: rows [4,7], S1 -> S0; own rows -> P[pb^1]; NO trailing bar --
        // each warp signals as soon as its own stores are done.
        if (v0s4) row_update(S1, S0, m0, o0, cf0, sb0, st0, gpo, go0,
                             isrc0, smask, source, t0 + 3);
        if (v1s4) row_update(S1, S0, m1, o1, cf1, sb1, st1, gpo, go1,
                             isrc1, smask, source, t0 + 3);
        warp_signal(bid, tid);             // counters += 24 (block b done)
    }

    // final deferred gather (last block's s4 result)
    __syncthreads();
    if (my_rec) outp[NSTEPS - 1] = S0[rec_off];
}

extern "C" void kernel_launch(void* const* d_in, const int* in_sizes, int n_in,
                              void* d_out, int out_size)
{
    const float* vel    = (const float*)d_in[0];
    const float* source = (const float*)d_in[1];
    const int*   srcx   = (const int*)d_in[2];
    const int*   srcz   = (const int*)d_in[3];
    const int*   rec_x  = (const int*)d_in[4];
    const int*   rec_z  = (const int*)d_in[5];
    float* out = (float*)d_out;

    cudaFuncSetAttribute(wave_fdtd_reg_kernel,
                         cudaFuncAttributeMaxDynamicSharedMemorySize, SMEM_BYTES);
    wave_fdtd_reg_kernel<<<NCTA, NTHR, SMEM_BYTES>>>(
        vel, source, srcx, srcz, rec_x, rec_z, out);
}

// round 17
// speedup vs baseline: 1.1704x; 1.1419x over previous
#include <cuda_runtime.h>
#include <cuda_bf16.h>
#include <cstdint>

// ---------------------------------------------------------------------------
// WaveFDTD2D, temporal blocking K=4, 128 persistent CTAs x 768 threads.
// R13 base (rows {ty, ty+6} per thread, m/o/cf register-resident, tid0-spin
// neighbor sync, hoisted invariants). R16: halo staging phase REMOVED --
// s1 reads halo neighbors straight from global (L2) via per-thread static
// source flags; interior neighbors from SMEM. 5 barriers/block instead of 6,
// halo L2 latency overlaps s1 interior compute.
// ---------------------------------------------------------------------------

#define NX      512
#define NZ      512
#define NSTEPS  512
#define NREC    128
#define KST     4
#define NBLK    (NSTEPS / KST)     // 128
#define NCTA    128
#define NTHR    768
#define RROWS   4
#define EXT     12
#define SROW    520
#define BUF     (EXT * SROW)
#define SMEM_FLOATS (2 * BUF)
#define SMEM_BYTES  (SMEM_FLOATS * 4)
#define PAD     32

__device__ __align__(16) float g_P[2][NX * NZ];
__device__ __align__(16) float g_Q[2][NX * NZ];
__device__ unsigned long long g_done[NCTA * PAD];   // monotonic, never reset

static __device__ __forceinline__ void signal_done(int bid) {
    asm volatile("red.add.release.gpu.u64 [%0], 1;"
                 :: "l"(&g_done[bid * PAD]) : "memory");
}

static __device__ __forceinline__ void wait_neighbors(int bid, unsigned long long tgt) {
    const unsigned long long* lo =
        (bid > 0) ? &g_done[(bid - 1) * PAD] : nullptr;
    const unsigned long long* hi =
        (bid < NCTA - 1) ? &g_done[(bid + 1) * PAD] : nullptr;
    bool need_lo = (lo != nullptr), need_hi = (hi != nullptr);
    while (need_lo || need_hi) {
        unsigned long long a = tgt, b = tgt;
        if (need_lo)
            asm volatile("ld.acquire.gpu.u64 %0, [%1];" : "=l"(a) : "l"(lo) : "memory");
        if (need_hi)
            asm volatile("ld.acquire.gpu.u64 %0, [%1];" : "=l"(b) : "l"(hi) : "memory");
        if (a >= tgt) need_lo = false;
        if (b >= tgt) need_hi = false;
    }
}

// Pure stencil math (reference arithmetic order).
static __device__ __forceinline__ float4 stencil4(
    const float4 m, const float4 o, const float4 cf,
    const float4 u, const float4 d, const float lf, const float rg)
{
    const float INV = 0.01f;   // 1/(dx*dz)
    float4 nw; float lap;
    lap  = ((((u.x + d.x) + lf)  + m.y) - 4.0f * m.x) * INV;
    nw.x = (2.0f * m.x - o.x) + cf.x * lap;
    lap  = ((((u.y + d.y) + m.x) + m.z) - 4.0f * m.y) * INV;
    nw.y = (2.0f * m.y - o.y) + cf.y * lap;
    lap  = ((((u.z + d.z) + m.y) + m.w) - 4.0f * m.z) * INV;
    nw.z = (2.0f * m.z - o.z) + cf.z * lap;
    lap  = ((((u.w + d.w) + m.z) + rg)  - 4.0f * m.w) * INV;
    nw.w = (2.0f * m.w - o.w) + cf.w * lap;
    return nw;
}

// Generic substep row (s2..s4): all neighbors from SMEM.
static __device__ __forceinline__ void row_update(
    const float* __restrict__ Scur, float* __restrict__ Snext,
    float4& m, float4& o, const float4 cf,
    const int sb,
    const bool do_store, float* __restrict__ gdst, const int go,
    const bool isrc, const float4 smask,
    const float* __restrict__ source, const int t)
{
    const float DT2f = 1.0e-6f;
    const float4 u  = *reinterpret_cast<const float4*>(Scur + sb - SROW);
    const float4 d  = *reinterpret_cast<const float4*>(Scur + sb + SROW);
    const float  lf = Scur[sb - 1];
    const float  rg = Scur[sb + 4];
    float4 nw = stencil4(m, o, cf, u, d, lf, rg);
    if (isrc) {
        const float sadd = __ldg(source + t) * DT2f;
        nw.x += smask.x * sadd;  nw.y += smask.y * sadd;
        nw.z += smask.z * sadd;  nw.w += smask.w * sadd;
    }
    *reinterpret_cast<float4*>(Snext + sb) = nw;
    if (do_store) __stcg(reinterpret_cast<float4*>(gdst + go), nw);
    o = m;  m = nw;
}

__global__ void __launch_bounds__(NTHR, 1)
wave_fdtd_reg_kernel(const float* __restrict__ vel,
                     const float* __restrict__ source,
                     const int*   __restrict__ p_srcx,
                     const int*   __restrict__ p_srcz,
                     const int*   __restrict__ rec_x,
                     const int*   __restrict__ rec_z,
                     float*       __restrict__ out)
{
    extern __shared__ float sm[];
    __shared__ unsigned long long sm_base;
    float* S0 = sm;
    float* S1 = sm + BUF;

    const int tid = threadIdx.x;
    const int bid = blockIdx.x;
    const int g0  = bid * RROWS;
    const int tx  = tid & 127;
    const int ty  = tid >> 7;        // 0..5
    const int colbase = 4 + tx * 4;

    const int sx = p_srcx[0];
    const int sz = p_srcz[0];

    const int r0 = ty;               // 0..5
    const int r1 = ty + 6;           // 6..11
    const int ga = g0 - 4 + r0;
    const int gb = g0 - 4 + r1;
    const bool ing0 = (unsigned)ga < (unsigned)NX;
    const bool ing1 = (unsigned)gb < (unsigned)NX;

    // ---- hoisted invariants ----
    const int sb0 = r0 * SROW + colbase;
    const int sb1 = r1 * SROW + colbase;
    const int go0 = ga * NZ + tx * 4;
    const int go1 = gb * NZ + tx * 4;
    const int clo = 4 - g0;
    const int chi = 515 - g0;

    const bool v0s1 = ing0 && (r0 >= ((clo > 1) ? clo : 1));
    const bool v0s2 = ing0 && (r0 >= ((clo > 2) ? clo : 2));
    const bool v0s3 = ing0 && (r0 >= ((clo > 3) ? clo : 3));
    const bool v0s4 = ing0 && (r0 >= 4);
    const bool v1s1 = ing1 && (r1 <= ((chi < 10) ? chi : 10));
    const bool v1s2 = ing1 && (r1 <= ((chi < 9) ? chi : 9));
    const bool v1s3 = ing1 && (r1 <= ((chi < 8) ? chi : 8));
    const bool v1s4 = ing1 && (r1 <= 7);

    const bool st0 = (r0 >= 4);
    const bool st1 = (r1 <= 7);

    // fused-s1 roles (register refresh for halo rows)
    const bool f0om  = (r0 == 3);
    const bool f0old = (r0 == 1) || (r0 == 2);
    const bool f1om  = (r1 == 8);
    const bool f1old = (r1 == 9) || (r1 == 10);

    // fused-s1 neighbor sources: global (gp) vs SMEM (S0)
    const bool u0g = (r0 <= 4), d0g = (r0 <= 2), l0g = (r0 <= 3);
    const bool u1g = (r1 >= 9), d1g = (r1 >= 7), l1g = (r1 >= 8);
    // zero-pad flags (grid edge rows / columns)
    const bool u0z = (ga - 1 < 0) || (ga - 1 > 511);
    const bool d0z = (ga + 1 < 0) || (ga + 1 > 511);
    const bool u1z = (gb - 1 < 0) || (gb - 1 > 511);
    const bool d1z = (gb + 1 < 0) || (gb + 1 > 511);
    const bool lx0 = (tx == 0);      // left column edge
    const bool rx0 = (tx == 127);    // right column edge

    // source injection
    const bool isrc0 = ing0 && (ga == sx) && ((sz >> 2) == tx);
    const bool isrc1 = ing1 && (gb == sx) && ((sz >> 2) == tx);
    const int  sl = sz & 3;
    const float4 smask = make_float4((sl == 0) ? 1.f : 0.f, (sl == 1) ? 1.f : 0.f,
                                     (sl == 2) ? 1.f : 0.f, (sl == 3) ? 1.f : 0.f);

    int my_rx = -1, my_rz = 0;
    if (tid < NREC) { my_rx = __ldg(rec_x + tid); my_rz = __ldg(rec_z + tid); }
    const bool my_rec = (my_rx >= 0) && ((my_rx >> 2) == bid);
    const int  rec_off = my_rec ? ((4 + (my_rx & 3)) * SROW + 4 + my_rz) : 0;
    float* const outp = out + (size_t)tid * NSTEPS;

    // ---- zero SMEM; read own counter base ----
    for (int i = tid; i < SMEM_FLOATS; i += NTHR) sm[i] = 0.0f;
    if (tid == 0) sm_base = g_done[bid * PAD];
    __syncthreads();
    const unsigned long long base = sm_base;

    // ---- register state ----
    const float DT2f = 1.0e-6f;
    const float4 z4 = make_float4(0.f, 0.f, 0.f, 0.f);
    float4 m0 = z4, o0 = z4, cf0 = z4;
    float4 m1 = z4, o1 = z4, cf1 = z4;
    if (ing0) {
        const float4 v = __ldg(reinterpret_cast<const float4*>(vel + go0));
        cf0 = make_float4(v.x*v.x*DT2f, v.y*v.y*DT2f, v.z*v.z*DT2f, v.w*v.w*DT2f);
    }
    if (ing1) {
        const float4 v = __ldg(reinterpret_cast<const float4*>(vel + go1));
        cf1 = make_float4(v.x*v.x*DT2f, v.y*v.y*DT2f, v.z*v.z*DT2f, v.w*v.w*DT2f);
    }

    // ---- zero OWN rows of global pair 0 ----
    if (tid < RROWS * 128) {
        const int r = tid >> 7, c = tid & 127;
        const int off = (g0 + r) * NZ + c * 4;
        __stcg(reinterpret_cast<float4*>(g_P[0] + off), z4);
        __stcg(reinterpret_cast<float4*>(g_Q[0] + off), z4);
    }
    __syncthreads();
    if (tid == 0) signal_done(bid);

    for (int b = 0; b < NBLK; ++b) {
        if (tid == 0)
            wait_neighbors(bid, base + 1 + (unsigned long long)b);
        __syncthreads();   // also makes prev s4's S0 rows 4..7 visible

        const int pb = b & 1;
        const float* gp = g_P[pb];
        const float* gq = g_Q[pb];
        float* gpo = g_P[pb ^ 1];
        float* gqo = g_Q[pb ^ 1];
        const int t0 = b * KST;

        // ================= s1 (fused halo): rows [1,10], -> S1 =============
        if (v0s1) {
            if (f0om)       { o0 = m0; m0 = __ldcg(reinterpret_cast<const float4*>(gp + go0)); }
            else if (f0old) { o0 = __ldcg(reinterpret_cast<const float4*>(gq + go0));
                              m0 = __ldcg(reinterpret_cast<const float4*>(gp + go0)); }
            const float4 u = u0z ? z4 : (u0g
                ? __ldcg(reinterpret_cast<const float4*>(gp + go0 - NZ))
                : *reinterpret_cast<const float4*>(S0 + sb0 - SROW));
            const float4 d = d0z ? z4 : (d0g
                ? __ldcg(reinterpret_cast<const float4*>(gp + go0 + NZ))
                : *reinterpret_cast<const float4*>(S0 + sb0 + SROW));
            const float lf = l0g ? (lx0 ? 0.0f : __ldcg(gp + go0 - 1)) : S0[sb0 - 1];
            const float rg = l0g ? (rx0 ? 0.0f : __ldcg(gp + go0 + 4)) : S0[sb0 + 4];
            float4 nw = stencil4(m0, o0, cf0, u, d, lf, rg);
            if (isrc0) {
                const float sadd = __ldg(source + t0) * DT2f;
                nw.x += smask.x * sadd;  nw.y += smask.y * sadd;
                nw.z += smask.z * sadd;  nw.w += smask.w * sadd;
            }
            *reinterpret_cast<float4*>(S1 + sb0) = nw;
            o0 = m0;  m0 = nw;
        }
        if (v1s1) {
            if (f1om)       { o1 = m1; m1 = __ldcg(reinterpret_cast<const float4*>(gp + go1)); }
            else if (f1old) { o1 = __ldcg(reinterpret_cast<const float4*>(gq + go1));
                              m1 = __ldcg(reinterpret_cast<const float4*>(gp + go1)); }
            const float4 u = u1z ? z4 : (u1g
                ? __ldcg(reinterpret_cast<const float4*>(gp + go1 - NZ))
                : *reinterpret_cast<const float4*>(S0 + sb1 - SROW));
            const float4 d = d1z ? z4 : (d1g
                ? __ldcg(reinterpret_cast<const float4*>(gp + go1 + NZ))
                : *reinterpret_cast<const float4*>(S0 + sb1 + SROW));
            const float lf = l1g ? (lx0 ? 0.0f : __ldcg(gp + go1 - 1)) : S0[sb1 - 1];
            const float rg = l1g ? (rx0 ? 0.0f : __ldcg(gp + go1 + 4)) : S0[sb1 + 4];
            float4 nw = stencil4(m1, o1, cf1, u, d, lf, rg);
            if (isrc1) {
                const float sadd = __ldg(source + t0) * DT2f;
                nw.x += smask.x * sadd;  nw.y += smask.y * sadd;
                nw.z += smask.z * sadd;  nw.w += smask.w * sadd;
            }
            *reinterpret_cast<float4*>(S1 + sb1) = nw;
            o1 = m1;  m1 = nw;
        }
        __syncthreads();
        if (my_rec) outp[t0] = S1[rec_off];

        // s2: rows [2,9], S1 -> S0
        if (v0s2) row_update(S1, S0, m0, o0, cf0, sb0, false, nullptr, 0,
                             isrc0, smask, source, t0 + 1);
        if (v1s2) row_update(S1, S0, m1, o1, cf1, sb1, false, nullptr, 0,
                             isrc1, smask, source, t0 + 1);
        __syncthreads();
        if (my_rec) outp[t0 + 1] = S0[rec_off];

        // s3: rows [3,8], S0 -> S1; own rows -> Q[pb^1]
        if (v0s3) row_update(S0, S1, m0, o0, cf0, sb0, st0, gqo, go0,
                             isrc0, smask, source, t0 + 2);
        if (v1s3) row_update(S0, S1, m1, o1, cf1, sb1, st1, gqo, go1,
                             isrc1, smask, source, t0 + 2);
        __syncthreads();
        if (my_rec) outp[t0 + 2] = S1[rec_off];

        // s4: rows [4,7], S1 -> S0; own rows -> P[pb^1]
        if (v0s4) row_update(S1, S0, m0, o0, cf0, sb0, st0, gpo, go0,
                             isrc0, smask, source, t0 + 3);
        if (v1s4) row_update(S1, S0, m1, o1, cf1, sb1, st1, gpo, go1,
                             isrc1, smask, source, t0 + 3);
        __syncthreads();
        if (my_rec) outp[t0 + 3] = S0[rec_off];

        if (tid == 0) signal_done(bid);
    }
}

extern "C" void kernel_launch(void* const* d_in, const int* in_sizes, int n_in,
                              void* d_out, int out_size)
{
    const float* vel    = (const float*)d_in[0];
    const float* source = (const float*)d_in[1];
    const int*   srcx   = (const int*)d_in[2];
    const int*   srcz   = (const int*)d_in[3];
    const int*   rec_x  = (const int*)d_in[4];
    const int*   rec_z  = (const int*)d_in[5];
    float* out = (float*)d_out;

    cudaFuncSetAttribute(wave_fdtd_reg_kernel,
                         cudaFuncAttributeMaxDynamicSharedMemorySize, SMEM_BYTES);
    wave_fdtd_reg_kernel<<<NCTA, NTHR, SMEM_BYTES>>>(
        vel, source, srcx, srcz, rec_x, rec_z, out);
}